// round 13
// baseline (speedup 1.0000x reference)
#include <cuda_runtime.h>
#include <cuda_fp16.h>
#include <cstdint>

#define HDIM    64
#define MTILE   256
#define THREADS 256
#define PWA     36
#define PWB     36
#define FMAX    128
#define BMAX    8192

typedef unsigned long long ull;

#define SA_WORDS (MTILE * PWA)          // 9216 words = 36 KB
#define SB_WORDS (HDIM * PWB)           // 2304 words = 9 KB
#define SMEM_BYTES ((SA_WORDS + SB_WORDS) * 4)

__device__ uint4 g_w2s[FMAX * (SB_WORDS / 4)];  // fp16 W2^T smem image per f
__device__ float g_xT[FMAX * BMAX];             // x transposed (F, B)
__device__ float g_fnnT[FMAX * BMAX];           // fnn transposed (F, B)

__device__ __forceinline__ void mma_f16(float* d, uint32_t a0, uint32_t a1,
                                        uint32_t a2, uint32_t a3,
                                        uint32_t b0, uint32_t b1) {
    asm volatile(
        "mma.sync.aligned.m16n8k16.row.col.f32.f16.f16.f32 "
        "{%0,%1,%2,%3}, {%4,%5,%6,%7}, {%8,%9}, {%0,%1,%2,%3};"
        : "+f"(d[0]), "+f"(d[1]), "+f"(d[2]), "+f"(d[3])
        : "r"(a0), "r"(a1), "r"(a2), "r"(a3), "r"(b0), "r"(b1));
}

// ---- prep: (blocks < F) W2[f]^T fp16 image; (rest) 32x32 transpose of x ----
__global__ void nam_prep(const float* __restrict__ W2,
                         const float* __restrict__ x, int B, int F)
{
    const int bid = blockIdx.x;
    const int tid = threadIdx.x;                  // 256 threads

    if (bid < F) {
        const float* W2f = W2 + (size_t)bid * HDIM * HDIM;
        uint32_t* img = reinterpret_cast<uint32_t*>(g_w2s) + (size_t)bid * SB_WORDS;
        #pragma unroll
        for (int it = 0; it < 8; ++it) {
            int p  = tid + it * 256;              // 0..2047
            int n  = p & 63;
            int hp = p >> 6;
            float v0 = W2f[(2 * hp) * HDIM + n];
            float v1 = W2f[(2 * hp + 1) * HDIM + n];
            __half2 h2 = __floats2half2_rn(v0, v1);
            img[n * PWB + hp] = *reinterpret_cast<uint32_t*>(&h2);
        }
        { int n = tid >> 2, j = tid & 3; img[n * PWB + 32 + j] = 0; }
    } else {
        __shared__ float tile[32][33];
        const int t  = bid - F;
        const int NB = B >> 5;
        const int fb = t / NB, bt = t % NB;
        const int tx = tid & 31, ty = tid >> 5;   // ty 0..7
        #pragma unroll
        for (int i = 0; i < 4; ++i) {
            int b = bt * 32 + ty + i * 8;
            tile[ty + i * 8][tx] = x[(size_t)b * F + fb * 32 + tx];
        }
        __syncthreads();
        #pragma unroll
        for (int i = 0; i < 4; ++i) {
            int f = fb * 32 + ty + i * 8;
            g_xT[(size_t)f * B + bt * 32 + tx] = tile[tx][ty + i * 8];
        }
    }
}

// One CTA = (feature f) x (256 batch rows). A = fp16(h1), B = fp16(W2^T),
// single-product m16n8k16 HMMA; fused bias+relu+W3 epilogue -> fnnT.
__global__ void __launch_bounds__(THREADS, 2) nam_mma(
    const float* __restrict__ W1,
    const float* __restrict__ b1,
    const float* __restrict__ b2,
    const float* __restrict__ W3,
    const float* __restrict__ b3,
    int B, int F)
{
    extern __shared__ __align__(16) uint32_t smw[];
    uint32_t* sAw = smw;             // [256][36]
    uint32_t* sBw = smw + SA_WORDS;  // [64][36]

    __shared__ float sw1[HDIM], sb1[HDIM], sb2[HDIM], sw3[HDIM];
    __shared__ float sb3v;

    const int f    = blockIdx.x;
    const int tid  = threadIdx.x;
    const int wid  = tid >> 5;
    const int lane = tid & 31;
    const int g    = lane >> 2;
    const int tig  = lane & 3;

    // ---- B tile: cp.async copy of precomputed fp16 image (overlaps layer1) ----
    {
        const uint4* src = g_w2s + (size_t)f * (SB_WORDS / 4);
        uint32_t dsm = (uint32_t)__cvta_generic_to_shared(sBw);
        #pragma unroll
        for (int i = tid; i < SB_WORDS / 4; i += THREADS) {
            asm volatile("cp.async.cg.shared.global [%0], [%1], 16;"
                         :: "r"(dsm + i * 16), "l"(src + i));
        }
        asm volatile("cp.async.commit_group;");
    }

    if (tid < HDIM) {
        sw1[tid] = W1[f * HDIM + tid];
        sb1[tid] = b1[f * HDIM + tid];
        sb2[tid] = b2[f * HDIM + tid];
        sw3[tid] = W3[f * HDIM + tid];
    }
    if (tid == 0) sb3v = b3[f];
    __syncthreads();   // sw1/sb1 ready

    // ---- A tile: layer 1, one batch row per thread (coalesced xT read) ----
    const float xv = g_xT[(size_t)f * B + blockIdx.y * MTILE + tid];
    #pragma unroll
    for (int jq = 0; jq < 8; ++jq) {
        uint32_t w[4];
        #pragma unroll
        for (int jj = 0; jj < 4; ++jj) {
            int j = jq * 4 + jj;
            float v0 = fmaxf(fmaf(xv, sw1[2 * j], sb1[2 * j]), 0.0f);
            float v1 = fmaxf(fmaf(xv, sw1[2 * j + 1], sb1[2 * j + 1]), 0.0f);
            __half2 h2v = __floats2half2_rn(v0, v1);
            w[jj] = *reinterpret_cast<uint32_t*>(&h2v);
        }
        *reinterpret_cast<uint4*>(sAw + tid * PWA + jq * 4) =
            make_uint4(w[0], w[1], w[2], w[3]);
    }
    asm volatile("cp.async.wait_group 0;");
    __syncthreads();

    // ---- main loop: warp owns 32 rows (2 m16 tiles) x 64 cols ----
    float d[2][8][4];
    #pragma unroll
    for (int mt = 0; mt < 2; ++mt)
        #pragma unroll
        for (int nt = 0; nt < 8; ++nt)
            #pragma unroll
            for (int q = 0; q < 4; ++q) d[mt][nt][q] = 0.0f;

    const int rowBase = wid * 32;

    #pragma unroll
    for (int ks = 0; ks < 4; ++ks) {
        const int w0 = ks * 8 + tig;
        uint32_t a[2][4];
        #pragma unroll
        for (int mt = 0; mt < 2; ++mt) {
            int r0 = rowBase + mt * 16 + g;
            a[mt][0] = sAw[r0 * PWA + w0];
            a[mt][1] = sAw[(r0 + 8) * PWA + w0];
            a[mt][2] = sAw[r0 * PWA + w0 + 4];
            a[mt][3] = sAw[(r0 + 8) * PWA + w0 + 4];
        }
        #pragma unroll
        for (int nt = 0; nt < 8; ++nt) {
            int n = nt * 8 + g;
            uint32_t b0 = sBw[n * PWB + w0];
            uint32_t b1 = sBw[n * PWB + w0 + 4];
            #pragma unroll
            for (int mt = 0; mt < 2; ++mt)
                mma_f16(d[mt][nt], a[mt][0], a[mt][1], a[mt][2], a[mt][3], b0, b1);
        }
    }

    // ---- epilogue: bias + relu + W3 dot -> smem stage -> coalesced fnnT ----
    __syncthreads();                 // done reading sAw
    float* sFn = reinterpret_cast<float*>(sAw);
    #pragma unroll
    for (int mt = 0; mt < 2; ++mt) {
        float s0 = 0.0f, s1 = 0.0f;
        #pragma unroll
        for (int nt = 0; nt < 8; ++nt) {
            int n0 = nt * 8 + 2 * tig;
            float bb0 = sb2[n0],     w30 = sw3[n0];
            float bb1 = sb2[n0 + 1], w31 = sw3[n0 + 1];
            s0 = fmaf(fmaxf(d[mt][nt][0] + bb0, 0.0f), w30, s0);
            s0 = fmaf(fmaxf(d[mt][nt][1] + bb1, 0.0f), w31, s0);
            s1 = fmaf(fmaxf(d[mt][nt][2] + bb0, 0.0f), w30, s1);
            s1 = fmaf(fmaxf(d[mt][nt][3] + bb1, 0.0f), w31, s1);
        }
        s0 += __shfl_xor_sync(0xFFFFFFFFu, s0, 1);
        s0 += __shfl_xor_sync(0xFFFFFFFFu, s0, 2);
        s1 += __shfl_xor_sync(0xFFFFFFFFu, s1, 1);
        s1 += __shfl_xor_sync(0xFFFFFFFFu, s1, 2);
        if (tig == 0) {
            int r = rowBase + mt * 16 + g;
            sFn[r]     = s0 + sb3v;
            sFn[r + 8] = s1 + sb3v;
        }
    }
    __syncthreads();
    g_fnnT[(size_t)f * B + blockIdx.y * MTILE + tid] = sFn[tid];
}

// finish: per 32-batch tile, out[b] = sum_f fnnT[f][b]; transpose to fnn (B,F).
__global__ void nam_finish(float* __restrict__ out, float* __restrict__ fnn,
                           int B, int F)
{
    __shared__ float tile[FMAX][33];
    __shared__ float ps[8][32];

    const int b0 = blockIdx.x * 32;
    const int t  = threadIdx.x;        // 256
    const int bl = t & 31, fc = t >> 5;  // fc 0..7

    float s = 0.0f;
    #pragma unroll
    for (int i = 0; i < 16; ++i) {
        int f = fc * 16 + i;
        float v = g_fnnT[(size_t)f * B + b0 + bl];
        s += v;
        tile[f][bl] = v;
    }
    ps[fc][bl] = s;
    __syncthreads();

    if (t < 32) {
        float o = 0.0f;
        #pragma unroll
        for (int i = 0; i < 8; ++i) o += ps[i][t];
        out[b0 + t] = o;
    }

    const int col = t & 127, rr = t >> 7;   // 2 rows per iteration
    #pragma unroll
    for (int r = 0; r < 32; r += 2)
        fnn[(size_t)(b0 + r + rr) * F + col] = tile[col][r + rr];
}

extern "C" void kernel_launch(void* const* d_in, const int* in_sizes, int n_in,
                              void* d_out, int out_size)
{
    const float* x  = (const float*)d_in[0];
    const float* W1 = (const float*)d_in[1];
    const float* b1 = (const float*)d_in[2];
    const float* W2 = (const float*)d_in[3];
    const float* b2 = (const float*)d_in[4];
    const float* W3 = (const float*)d_in[5];
    const float* b3 = (const float*)d_in[6];

    const int F = in_sizes[6];
    const int B = in_sizes[0] / F;

    float* out = (float*)d_out;   // (B,)
    float* fnn = out + B;         // (B, F)

    cudaFuncSetAttribute(nam_mma, cudaFuncAttributeMaxDynamicSharedMemorySize,
                         SMEM_BYTES);

    const int tBlocks = (F / 32) * (B / 32);
    nam_prep<<<F + tBlocks, 256>>>(W2, x, B, F);

    dim3 grid(F, B / MTILE);
    nam_mma<<<grid, THREADS, SMEM_BYTES>>>(W1, b1, b2, W3, b3, B, F);

    nam_finish<<<B / 32, 256>>>(out, fnn, B, F);
}

// round 14
// speedup vs baseline: 1.0099x; 1.0099x over previous
#include <cuda_runtime.h>
#include <cuda_fp16.h>
#include <cstdint>

#define HDIM    64
#define MTILE   128
#define THREADS 128
#define PWA     36
#define PWB     36
#define FMAX    128
#define BMAX    8192

typedef unsigned long long ull;

#define SA_WORDS (MTILE * PWA)          // 4608 words = 18 KB
#define SB_WORDS (HDIM * PWB)           // 2304 words = 9 KB
#define SMEM_BYTES ((SA_WORDS + SB_WORDS) * 4)

__device__ uint4 g_w2s[FMAX * (SB_WORDS / 4)];  // fp16 W2^T smem image per f
__device__ float g_xT[FMAX * BMAX];             // x transposed (F, B)
__device__ float g_fnnT[FMAX * BMAX];           // fnn transposed (F, B)

__device__ __forceinline__ void mma_f16(float* d, uint32_t a0, uint32_t a1,
                                        uint32_t a2, uint32_t a3,
                                        uint32_t b0, uint32_t b1) {
    asm volatile(
        "mma.sync.aligned.m16n8k16.row.col.f32.f16.f16.f32 "
        "{%0,%1,%2,%3}, {%4,%5,%6,%7}, {%8,%9}, {%0,%1,%2,%3};"
        : "+f"(d[0]), "+f"(d[1]), "+f"(d[2]), "+f"(d[3])
        : "r"(a0), "r"(a1), "r"(a2), "r"(a3), "r"(b0), "r"(b1));
}

// ---- prep: (blocks < F) W2[f]^T fp16 image via smem stage (coalesced both
// ways); (rest) 32x32 transpose of x ----
__global__ void nam_prep(const float* __restrict__ W2,
                         const float* __restrict__ x, int B, int F)
{
    const int bid = blockIdx.x;
    const int tid = threadIdx.x;                  // 256 threads

    if (bid < F) {
        __shared__ float sW2[HDIM * HDIM];        // 16 KB, row-major [h][n]
        const float4* src4 = reinterpret_cast<const float4*>(
            W2 + (size_t)bid * HDIM * HDIM);
        float4* dst4 = reinterpret_cast<float4*>(sW2);
        #pragma unroll
        for (int i = 0; i < 4; ++i)               // 1024 float4, coalesced
            dst4[tid + i * 256] = src4[tid + i * 256];
        __syncthreads();

        uint32_t* img = reinterpret_cast<uint32_t*>(g_w2s) + (size_t)bid * SB_WORDS;
        #pragma unroll
        for (int i = 0; i < 9; ++i) {             // 2304 words, write-order
            int w = tid + i * 256;
            int n = w / PWB;                      // const-div -> mul/shift
            int m = w - n * PWB;
            uint32_t val = 0;
            if (m < 32) {
                __half2 h2 = __floats2half2_rn(sW2[(2 * m) * HDIM + n],
                                               sW2[(2 * m + 1) * HDIM + n]);
                val = *reinterpret_cast<uint32_t*>(&h2);
            }
            img[w] = val;                         // fully coalesced
        }
    } else {
        __shared__ float tile[32][33];
        const int t  = bid - F;
        const int NB = B >> 5;
        const int fb = t / NB, bt = t % NB;
        const int tx = tid & 31, ty = tid >> 5;   // ty 0..7
        #pragma unroll
        for (int i = 0; i < 4; ++i) {
            int b = bt * 32 + ty + i * 8;
            tile[ty + i * 8][tx] = x[(size_t)b * F + fb * 32 + tx];
        }
        __syncthreads();
        #pragma unroll
        for (int i = 0; i < 4; ++i) {
            int f = fb * 32 + ty + i * 8;
            g_xT[(size_t)f * B + bt * 32 + tx] = tile[tx][ty + i * 8];
        }
    }
}

// One CTA = (feature f) x (128 batch rows). A = fp16(h1), B = fp16(W2^T),
// single-product m16n8k16 HMMA; fused bias+relu+W3 epilogue -> fnnT.
__global__ void __launch_bounds__(THREADS, 4) nam_mma(
    const float* __restrict__ W1,
    const float* __restrict__ b1,
    const float* __restrict__ b2,
    const float* __restrict__ W3,
    const float* __restrict__ b3,
    int B, int F)
{
    extern __shared__ __align__(16) uint32_t smw[];
    uint32_t* sAw = smw;             // [128][36]
    uint32_t* sBw = smw + SA_WORDS;  // [64][36]

    __shared__ float sw1[HDIM], sb1[HDIM], sb2[HDIM], sw3[HDIM];
    __shared__ float sb3v;

    const int f    = blockIdx.x;
    const int tid  = threadIdx.x;
    const int wid  = tid >> 5;
    const int lane = tid & 31;
    const int g    = lane >> 2;
    const int tig  = lane & 3;

    // hoist the independent x load so its latency overlaps the prologue
    const float xv = g_xT[(size_t)f * B + blockIdx.y * MTILE + tid];

    if (tid < HDIM) {
        sw1[tid] = W1[f * HDIM + tid];
        sb1[tid] = b1[f * HDIM + tid];
        sb2[tid] = b2[f * HDIM + tid];
        sw3[tid] = W3[f * HDIM + tid];
    }
    if (tid == 0) sb3v = b3[f];

    // ---- B tile: vector copy of precomputed fp16 image ----
    {
        const uint4* src = g_w2s + (size_t)f * (SB_WORDS / 4);
        uint4* dst = reinterpret_cast<uint4*>(sBw);
        #pragma unroll
        for (int i = tid; i < SB_WORDS / 4; i += THREADS)
            dst[i] = src[i];
    }
    __syncthreads();

    // ---- A tile: layer 1, one batch row per thread ----
    #pragma unroll
    for (int jq = 0; jq < 8; ++jq) {
        uint32_t w[4];
        #pragma unroll
        for (int jj = 0; jj < 4; ++jj) {
            int j = jq * 4 + jj;
            float v0 = fmaxf(fmaf(xv, sw1[2 * j], sb1[2 * j]), 0.0f);
            float v1 = fmaxf(fmaf(xv, sw1[2 * j + 1], sb1[2 * j + 1]), 0.0f);
            __half2 h2v = __floats2half2_rn(v0, v1);
            w[jj] = *reinterpret_cast<uint32_t*>(&h2v);
        }
        *reinterpret_cast<uint4*>(sAw + tid * PWA + jq * 4) =
            make_uint4(w[0], w[1], w[2], w[3]);
    }
    __syncthreads();

    // ---- main loop: warp owns 32 rows (2 m16 tiles) x 64 cols ----
    float d[2][8][4];
    #pragma unroll
    for (int mt = 0; mt < 2; ++mt)
        #pragma unroll
        for (int nt = 0; nt < 8; ++nt)
            #pragma unroll
            for (int q = 0; q < 4; ++q) d[mt][nt][q] = 0.0f;

    const int rowBase = wid * 32;

    #pragma unroll
    for (int ks = 0; ks < 4; ++ks) {
        const int w0 = ks * 8 + tig;
        uint32_t a[2][4];
        #pragma unroll
        for (int mt = 0; mt < 2; ++mt) {
            int r0 = rowBase + mt * 16 + g;
            a[mt][0] = sAw[r0 * PWA + w0];
            a[mt][1] = sAw[(r0 + 8) * PWA + w0];
            a[mt][2] = sAw[r0 * PWA + w0 + 4];
            a[mt][3] = sAw[(r0 + 8) * PWA + w0 + 4];
        }
        #pragma unroll
        for (int nt = 0; nt < 8; ++nt) {
            int n = nt * 8 + g;
            uint32_t b0 = sBw[n * PWB + w0];
            uint32_t b1 = sBw[n * PWB + w0 + 4];
            #pragma unroll
            for (int mt = 0; mt < 2; ++mt)
                mma_f16(d[mt][nt], a[mt][0], a[mt][1], a[mt][2], a[mt][3], b0, b1);
        }
    }

    // ---- epilogue: bias + relu + W3 dot -> smem stage -> coalesced fnnT ----
    __syncthreads();                 // done reading sAw
    float* sFn = reinterpret_cast<float*>(sAw);
    #pragma unroll
    for (int mt = 0; mt < 2; ++mt) {
        float s0 = 0.0f, s1 = 0.0f;
        #pragma unroll
        for (int nt = 0; nt < 8; ++nt) {
            int n0 = nt * 8 + 2 * tig;
            float bb0 = sb2[n0],     w30 = sw3[n0];
            float bb1 = sb2[n0 + 1], w31 = sw3[n0 + 1];
            s0 = fmaf(fmaxf(d[mt][nt][0] + bb0, 0.0f), w30, s0);
            s0 = fmaf(fmaxf(d[mt][nt][1] + bb1, 0.0f), w31, s0);
            s1 = fmaf(fmaxf(d[mt][nt][2] + bb0, 0.0f), w30, s1);
            s1 = fmaf(fmaxf(d[mt][nt][3] + bb1, 0.0f), w31, s1);
        }
        s0 += __shfl_xor_sync(0xFFFFFFFFu, s0, 1);
        s0 += __shfl_xor_sync(0xFFFFFFFFu, s0, 2);
        s1 += __shfl_xor_sync(0xFFFFFFFFu, s1, 1);
        s1 += __shfl_xor_sync(0xFFFFFFFFu, s1, 2);
        if (tig == 0) {
            int r = rowBase + mt * 16 + g;
            sFn[r]     = s0 + sb3v;
            sFn[r + 8] = s1 + sb3v;
        }
    }
    __syncthreads();
    g_fnnT[(size_t)f * B + blockIdx.y * MTILE + tid] = sFn[tid];
}

// finish: per 32-batch tile, out[b] = sum_f fnnT[f][b]; transpose to fnn (B,F).
__global__ void nam_finish(float* __restrict__ out, float* __restrict__ fnn,
                           int B, int F)
{
    __shared__ float tile[FMAX][33];
    __shared__ float ps[8][32];

    const int b0 = blockIdx.x * 32;
    const int t  = threadIdx.x;        // 256
    const int bl = t & 31, fc = t >> 5;  // fc 0..7

    float s = 0.0f;
    #pragma unroll
    for (int i = 0; i < 16; ++i) {
        int f = fc * 16 + i;
        float v = g_fnnT[(size_t)f * B + b0 + bl];
        s += v;
        tile[f][bl] = v;
    }
    ps[fc][bl] = s;
    __syncthreads();

    if (t < 32) {
        float o = 0.0f;
        #pragma unroll
        for (int i = 0; i < 8; ++i) o += ps[i][t];
        out[b0 + t] = o;
    }

    const int col = t & 127, rr = t >> 7;   // 2 rows per iteration
    #pragma unroll
    for (int r = 0; r < 32; r += 2)
        fnn[(size_t)(b0 + r + rr) * F + col] = tile[col][r + rr];
}

extern "C" void kernel_launch(void* const* d_in, const int* in_sizes, int n_in,
                              void* d_out, int out_size)
{
    const float* x  = (const float*)d_in[0];
    const float* W1 = (const float*)d_in[1];
    const float* b1 = (const float*)d_in[2];
    const float* W2 = (const float*)d_in[3];
    const float* b2 = (const float*)d_in[4];
    const float* W3 = (const float*)d_in[5];
    const float* b3 = (const float*)d_in[6];

    const int F = in_sizes[6];
    const int B = in_sizes[0] / F;

    float* out = (float*)d_out;   // (B,)
    float* fnn = out + B;         // (B, F)

    cudaFuncSetAttribute(nam_mma, cudaFuncAttributeMaxDynamicSharedMemorySize,
                         SMEM_BYTES);

    const int tBlocks = (F / 32) * (B / 32);
    nam_prep<<<F + tBlocks, 256>>>(W2, x, B, F);

    dim3 grid(F, B / MTILE);
    nam_mma<<<grid, THREADS, SMEM_BYTES>>>(W1, b1, b2, W3, b3, B, F);

    nam_finish<<<B / 32, 256>>>(out, fnn, B, F);
}

// round 15
// speedup vs baseline: 1.0903x; 1.0796x over previous
#include <cuda_runtime.h>
#include <cuda_fp16.h>
#include <cstdint>

#define HDIM    64
#define MTILE   128
#define THREADS 128
#define PWA     36
#define PWB     36
#define FMAX    128
#define BMAX    8192

typedef unsigned long long ull;

#define SA_WORDS (MTILE * PWA)          // 4608 words = 18 KB
#define SB_WORDS (HDIM * PWB)           // 2304 words = 9 KB
#define SMEM_BYTES ((SA_WORDS + SB_WORDS) * 4)

__device__ uint4 g_w2s[FMAX * (SB_WORDS / 4)];  // fp16 W2^T smem image per f
__device__ float g_xT[FMAX * BMAX];             // x transposed (F, B)
__device__ float g_fnnT[FMAX * BMAX];           // fnn transposed (F, B)

__device__ __forceinline__ void mma_f16(float* d, uint32_t a0, uint32_t a1,
                                        uint32_t a2, uint32_t a3,
                                        uint32_t b0, uint32_t b1) {
    asm volatile(
        "mma.sync.aligned.m16n8k16.row.col.f32.f16.f16.f32 "
        "{%0,%1,%2,%3}, {%4,%5,%6,%7}, {%8,%9}, {%0,%1,%2,%3};"
        : "+f"(d[0]), "+f"(d[1]), "+f"(d[2]), "+f"(d[3])
        : "r"(a0), "r"(a1), "r"(a2), "r"(a3), "r"(b0), "r"(b1));
}

// ---- prep: (blocks < F) W2[f]^T fp16 image via TRANSPOSED smem stage
// (conflict-free STS, <=2-way LDS, coalesced STG); (rest) 32x32 x-transpose ----
__global__ void nam_prep(const float* __restrict__ W2,
                         const float* __restrict__ x, int B, int F)
{
    const int bid = blockIdx.x;
    const int tid = threadIdx.x;                  // 256 threads

    if (bid < F) {
        __shared__ float sW2T[HDIM * 65];         // [n][h], pitch 65
        const float* W2f = W2 + (size_t)bid * HDIM * HDIM;
        #pragma unroll
        for (int it = 0; it < 16; ++it) {         // 4096 scalar, coalesced LDG
            int i = tid + it * 256;
            int h = i >> 6, n = i & 63;
            sW2T[n * 65 + h] = W2f[i];            // banks (n+h)%32: conflict-free
        }
        __syncthreads();

        uint32_t* img = reinterpret_cast<uint32_t*>(g_w2s) + (size_t)bid * SB_WORDS;
        #pragma unroll
        for (int it = 0; it < 9; ++it) {          // 2304 words in write-order
            int w = tid + it * 256;
            int n = w / PWB;
            int m = w - n * PWB;
            uint32_t val = 0;
            if (m < 32) {
                __half2 h2 = __floats2half2_rn(sW2T[n * 65 + 2 * m],
                                               sW2T[n * 65 + 2 * m + 1]);
                val = *reinterpret_cast<uint32_t*>(&h2);
            }
            img[w] = val;                         // fully coalesced STG
        }
    } else {
        __shared__ float tile[32][33];
        const int t  = bid - F;
        const int NB = B >> 5;
        const int fb = t / NB, bt = t % NB;
        const int tx = tid & 31, ty = tid >> 5;   // ty 0..7
        #pragma unroll
        for (int i = 0; i < 4; ++i) {
            int b = bt * 32 + ty + i * 8;
            tile[ty + i * 8][tx] = x[(size_t)b * F + fb * 32 + tx];
        }
        __syncthreads();
        #pragma unroll
        for (int i = 0; i < 4; ++i) {
            int f = fb * 32 + ty + i * 8;
            g_xT[(size_t)f * B + bt * 32 + tx] = tile[tx][ty + i * 8];
        }
    }
}

// One CTA = (feature f) x (128 batch rows). A = fp16(h1), B = fp16(W2^T),
// single-product m16n8k16 HMMA; fused bias+relu+W3 epilogue -> fnnT.
// (exact R9 shape — best measured main kernel)
__global__ void __launch_bounds__(THREADS, 4) nam_mma(
    const float* __restrict__ W1,
    const float* __restrict__ b1,
    const float* __restrict__ b2,
    const float* __restrict__ W3,
    const float* __restrict__ b3,
    int B, int F)
{
    extern __shared__ __align__(16) uint32_t smw[];
    uint32_t* sAw = smw;             // [128][36]
    uint32_t* sBw = smw + SA_WORDS;  // [64][36]

    __shared__ float sw1[HDIM], sb1[HDIM], sb2[HDIM], sw3[HDIM];
    __shared__ float sb3v;

    const int f    = blockIdx.x;
    const int tid  = threadIdx.x;
    const int wid  = tid >> 5;
    const int lane = tid & 31;
    const int g    = lane >> 2;
    const int tig  = lane & 3;

    if (tid < HDIM) {
        sw1[tid] = W1[f * HDIM + tid];
        sb1[tid] = b1[f * HDIM + tid];
        sb2[tid] = b2[f * HDIM + tid];
        sw3[tid] = W3[f * HDIM + tid];
    }
    if (tid == 0) sb3v = b3[f];

    // ---- B tile: vector copy of precomputed fp16 image ----
    {
        const uint4* src = g_w2s + (size_t)f * (SB_WORDS / 4);
        uint4* dst = reinterpret_cast<uint4*>(sBw);
        #pragma unroll
        for (int i = tid; i < SB_WORDS / 4; i += THREADS)
            dst[i] = src[i];
    }
    __syncthreads();

    // ---- A tile: layer 1, one batch row per thread (coalesced xT read) ----
    const float xv = g_xT[(size_t)f * B + blockIdx.y * MTILE + tid];
    #pragma unroll
    for (int jq = 0; jq < 8; ++jq) {
        uint32_t w[4];
        #pragma unroll
        for (int jj = 0; jj < 4; ++jj) {
            int j = jq * 4 + jj;
            float v0 = fmaxf(fmaf(xv, sw1[2 * j], sb1[2 * j]), 0.0f);
            float v1 = fmaxf(fmaf(xv, sw1[2 * j + 1], sb1[2 * j + 1]), 0.0f);
            __half2 h2v = __floats2half2_rn(v0, v1);
            w[jj] = *reinterpret_cast<uint32_t*>(&h2v);
        }
        *reinterpret_cast<uint4*>(sAw + tid * PWA + jq * 4) =
            make_uint4(w[0], w[1], w[2], w[3]);
    }
    __syncthreads();

    // ---- main loop: warp owns 32 rows (2 m16 tiles) x 64 cols ----
    float d[2][8][4];
    #pragma unroll
    for (int mt = 0; mt < 2; ++mt)
        #pragma unroll
        for (int nt = 0; nt < 8; ++nt)
            #pragma unroll
            for (int q = 0; q < 4; ++q) d[mt][nt][q] = 0.0f;

    const int rowBase = wid * 32;

    #pragma unroll
    for (int ks = 0; ks < 4; ++ks) {
        const int w0 = ks * 8 + tig;
        uint32_t a[2][4];
        #pragma unroll
        for (int mt = 0; mt < 2; ++mt) {
            int r0 = rowBase + mt * 16 + g;
            a[mt][0] = sAw[r0 * PWA + w0];
            a[mt][1] = sAw[(r0 + 8) * PWA + w0];
            a[mt][2] = sAw[r0 * PWA + w0 + 4];
            a[mt][3] = sAw[(r0 + 8) * PWA + w0 + 4];
        }
        #pragma unroll
        for (int nt = 0; nt < 8; ++nt) {
            int n = nt * 8 + g;
            uint32_t b0 = sBw[n * PWB + w0];
            uint32_t b1 = sBw[n * PWB + w0 + 4];
            #pragma unroll
            for (int mt = 0; mt < 2; ++mt)
                mma_f16(d[mt][nt], a[mt][0], a[mt][1], a[mt][2], a[mt][3], b0, b1);
        }
    }

    // ---- epilogue: bias + relu + W3 dot -> smem stage -> coalesced fnnT ----
    __syncthreads();                 // done reading sAw
    float* sFn = reinterpret_cast<float*>(sAw);
    #pragma unroll
    for (int mt = 0; mt < 2; ++mt) {
        float s0 = 0.0f, s1 = 0.0f;
        #pragma unroll
        for (int nt = 0; nt < 8; ++nt) {
            int n0 = nt * 8 + 2 * tig;
            float bb0 = sb2[n0],     w30 = sw3[n0];
            float bb1 = sb2[n0 + 1], w31 = sw3[n0 + 1];
            s0 = fmaf(fmaxf(d[mt][nt][0] + bb0, 0.0f), w30, s0);
            s0 = fmaf(fmaxf(d[mt][nt][1] + bb1, 0.0f), w31, s0);
            s1 = fmaf(fmaxf(d[mt][nt][2] + bb0, 0.0f), w30, s1);
            s1 = fmaf(fmaxf(d[mt][nt][3] + bb1, 0.0f), w31, s1);
        }
        s0 += __shfl_xor_sync(0xFFFFFFFFu, s0, 1);
        s0 += __shfl_xor_sync(0xFFFFFFFFu, s0, 2);
        s1 += __shfl_xor_sync(0xFFFFFFFFu, s1, 1);
        s1 += __shfl_xor_sync(0xFFFFFFFFu, s1, 2);
        if (tig == 0) {
            int r = rowBase + mt * 16 + g;
            sFn[r]     = s0 + sb3v;
            sFn[r + 8] = s1 + sb3v;
        }
    }
    __syncthreads();
    g_fnnT[(size_t)f * B + blockIdx.y * MTILE + tid] = sFn[tid];
}

// finish: per 32-batch tile, out[b] = sum_f fnnT[f][b]; transpose to fnn (B,F).
__global__ void nam_finish(float* __restrict__ out, float* __restrict__ fnn,
                           int B, int F)
{
    __shared__ float tile[FMAX][33];
    __shared__ float ps[8][32];

    const int b0 = blockIdx.x * 32;
    const int t  = threadIdx.x;        // 256
    const int bl = t & 31, fc = t >> 5;  // fc 0..7

    float s = 0.0f;
    #pragma unroll
    for (int i = 0; i < 16; ++i) {
        int f = fc * 16 + i;
        float v = g_fnnT[(size_t)f * B + b0 + bl];
        s += v;
        tile[f][bl] = v;
    }
    ps[fc][bl] = s;
    __syncthreads();

    if (t < 32) {
        float o = 0.0f;
        #pragma unroll
        for (int i = 0; i < 8; ++i) o += ps[i][t];
        out[b0 + t] = o;
    }

    const int col = t & 127, rr = t >> 7;   // 2 rows per iteration
    #pragma unroll
    for (int r = 0; r < 32; r += 2)
        fnn[(size_t)(b0 + r + rr) * F + col] = tile[col][r + rr];
}

extern "C" void kernel_launch(void* const* d_in, const int* in_sizes, int n_in,
                              void* d_out, int out_size)
{
    const float* x  = (const float*)d_in[0];
    const float* W1 = (const float*)d_in[1];
    const float* b1 = (const float*)d_in[2];
    const float* W2 = (const float*)d_in[3];
    const float* b2 = (const float*)d_in[4];
    const float* W3 = (const float*)d_in[5];
    const float* b3 = (const float*)d_in[6];

    const int F = in_sizes[6];
    const int B = in_sizes[0] / F;

    float* out = (float*)d_out;   // (B,)
    float* fnn = out + B;         // (B, F)

    cudaFuncSetAttribute(nam_mma, cudaFuncAttributeMaxDynamicSharedMemorySize,
                         SMEM_BYTES);

    const int tBlocks = (F / 32) * (B / 32);
    nam_prep<<<F + tBlocks, 256>>>(W2, x, B, F);

    dim3 grid(F, B / MTILE);
    nam_mma<<<grid, THREADS, SMEM_BYTES>>>(W1, b1, b2, W3, b3, B, F);

    nam_finish<<<B / 32, 256>>>(out, fnn, B, F);
}

// round 17
// speedup vs baseline: 1.1051x; 1.0136x over previous
#include <cuda_runtime.h>
#include <cuda_fp16.h>
#include <cstdint>

#define HDIM    64
#define MTILE   128
#define THREADS 128
#define FMAX    128
#define BMAX    8192

typedef unsigned long long ull;

// A tile: fragment-ordered quads. quad(t,ks,g,tig) = 4 words:
//   {row 16t+g @ word j, row 16t+8+g @ j, row 16t+g @ j+4, row 16t+8+g @ j+4},
//   j = 8ks+tig  (word = half2 of h-values 2j,2j+1)
// B tile: pair(nt,ks,g,tig) = {n=8nt+g @ j, n @ j+4}
#define SA_WORDS 4096    // 16 KB
#define SB_WORDS 2048    // 8 KB
#define SMEM_BYTES ((SA_WORDS + SB_WORDS) * 4)

__device__ uint4 g_w2s[FMAX * (SB_WORDS / 4)];  // fragment-ordered fp16 W2^T
__device__ float g_xT[FMAX * BMAX];             // x transposed (F, B)
__device__ float g_fnnT[FMAX * BMAX];           // fnn transposed (F, B)

__device__ __forceinline__ void mma_f16(float* d, uint32_t a0, uint32_t a1,
                                        uint32_t a2, uint32_t a3,
                                        uint32_t b0, uint32_t b1) {
    asm volatile(
        "mma.sync.aligned.m16n8k16.row.col.f32.f16.f16.f32 "
        "{%0,%1,%2,%3}, {%4,%5,%6,%7}, {%8,%9}, {%0,%1,%2,%3};"
        : "+f"(d[0]), "+f"(d[1]), "+f"(d[2]), "+f"(d[3])
        : "r"(a0), "r"(a1), "r"(a2), "r"(a3), "r"(b0), "r"(b1));
}

// ---- prep: (blocks < F) fragment-ordered W2 image via transposed smem
// stage; (rest) 32x32 x-transpose ----
__global__ void nam_prep(const float* __restrict__ W2,
                         const float* __restrict__ x, int B, int F)
{
    const int bid = blockIdx.x;
    const int tid = threadIdx.x;                  // 256 threads

    if (bid < F) {
        __shared__ float sW2T[HDIM * 65];         // [n][h], pitch 65
        const float* W2f = W2 + (size_t)bid * HDIM * HDIM;
        #pragma unroll
        for (int it = 0; it < 16; ++it) {         // coalesced LDG, cf STS
            int i = tid + it * 256;
            int h = i >> 6, n = i & 63;
            sW2T[n * 65 + h] = W2f[i];
        }
        __syncthreads();

        uint32_t* img = reinterpret_cast<uint32_t*>(g_w2s) + (size_t)bid * SB_WORDS;
        #pragma unroll
        for (int it = 0; it < 8; ++it) {          // write-order, coalesced STG
            int w  = tid + it * 256;
            int hh = w & 1, tg = (w >> 1) & 3, g = (w >> 3) & 7;
            int ks = (w >> 6) & 3, nt = w >> 8;
            int n = 8 * nt + g;
            int j = 8 * ks + tg + 4 * hh;
            __half2 h2 = __floats2half2_rn(sW2T[n * 65 + 2 * j],
                                           sW2T[n * 65 + 2 * j + 1]);
            img[w] = *reinterpret_cast<uint32_t*>(&h2);
        }
    } else {
        __shared__ float tile[32][33];
        const int t  = bid - F;
        const int NB = B >> 5;
        const int fb = t / NB, bt = t % NB;
        const int tx = tid & 31, ty = tid >> 5;
        #pragma unroll
        for (int i = 0; i < 4; ++i) {
            int b = bt * 32 + ty + i * 8;
            tile[ty + i * 8][tx] = x[(size_t)b * F + fb * 32 + tx];
        }
        __syncthreads();
        #pragma unroll
        for (int i = 0; i < 4; ++i) {
            int f = fb * 32 + ty + i * 8;
            g_xT[(size_t)f * B + bt * 32 + tx] = tile[tx][ty + i * 8];
        }
    }
}

// One CTA = (feature f) x (128 batch rows). Fragment-ordered A/B smem:
// mainloop = 1 LDS.128 (A) + 1 LDS.64 (B) per fragment, single-product HMMA.
__global__ void __launch_bounds__(THREADS, 4) nam_mma(
    const float* __restrict__ W1,
    const float* __restrict__ b1,
    const float* __restrict__ b2,
    const float* __restrict__ W3,
    const float* __restrict__ b3,
    int B, int F)
{
    extern __shared__ __align__(16) uint32_t smw[];
    uint32_t* sAw = smw;             // 4096 words, fragment quads
    uint32_t* sBw = smw + SA_WORDS;  // 2048 words, fragment pairs

    __shared__ float sw1[HDIM], sb1[HDIM], sb2[HDIM], sw3[HDIM];
    __shared__ float sb3v;

    const int f    = blockIdx.x;
    const int tid  = threadIdx.x;
    const int wid  = tid >> 5;
    const int lane = tid & 31;
    const int g    = lane >> 2;
    const int tig  = lane & 3;
    const size_t fB = (size_t)f * B;
    const int yBase = blockIdx.y * MTILE;

    if (tid < HDIM) {
        sw1[tid] = W1[f * HDIM + tid];
        sb1[tid] = b1[f * HDIM + tid];
        sb2[tid] = b2[f * HDIM + tid];
        sw3[tid] = W3[f * HDIM + tid];
    }
    if (tid == 0) sb3v = b3[f];

    // ---- B tile: vector copy of precomputed fragment-ordered image ----
    {
        const uint4* src = g_w2s + (size_t)f * (SB_WORDS / 4);
        uint4* dst = reinterpret_cast<uint4*>(sBw);
        #pragma unroll
        for (int i = 0; i < 4; ++i)
            dst[tid + i * THREADS] = src[tid + i * THREADS];
    }
    __syncthreads();   // sw1/sb1 ready

    // ---- layer 1 directly into fragment order: thread handles 2 combos ----
    #pragma unroll
    for (int cc = 0; cc < 2; ++cc) {
        int c    = tid + cc * THREADS;        // combo (t,g,tig)
        int ctig = c & 3, cg = (c >> 2) & 7, ct = c >> 5;
        int r0 = ct * 16 + cg;
        float x0 = g_xT[fB + yBase + r0];
        float x1 = g_xT[fB + yBase + r0 + 8];
        #pragma unroll
        for (int ks = 0; ks < 4; ++ks) {
            int j = 8 * ks + ctig;
            int h0 = 2 * j, h2 = 2 * j + 8;
            float w00 = sw1[h0],   bb00 = sb1[h0];
            float w01 = sw1[h0+1], bb01 = sb1[h0+1];
            float w20 = sw1[h2],   bb20 = sb1[h2];
            float w21 = sw1[h2+1], bb21 = sb1[h2+1];
            __half2 q0 = __floats2half2_rn(
                fmaxf(fmaf(x0, w00, bb00), 0.f), fmaxf(fmaf(x0, w01, bb01), 0.f));
            __half2 q1 = __floats2half2_rn(
                fmaxf(fmaf(x1, w00, bb00), 0.f), fmaxf(fmaf(x1, w01, bb01), 0.f));
            __half2 q2 = __floats2half2_rn(
                fmaxf(fmaf(x0, w20, bb20), 0.f), fmaxf(fmaf(x0, w21, bb21), 0.f));
            __half2 q3 = __floats2half2_rn(
                fmaxf(fmaf(x1, w20, bb20), 0.f), fmaxf(fmaf(x1, w21, bb21), 0.f));
            int qidx = ((ct * 4 + ks) * 8 + cg) * 4 + ctig;  // uint4 index
            reinterpret_cast<uint4*>(sAw)[qidx] =
                make_uint4(*reinterpret_cast<uint32_t*>(&q0),
                           *reinterpret_cast<uint32_t*>(&q1),
                           *reinterpret_cast<uint32_t*>(&q2),
                           *reinterpret_cast<uint32_t*>(&q3));
        }
    }
    __syncthreads();

    // ---- main loop: warp owns 32 rows (2 m16 tiles) x 64 cols ----
    float d[2][8][4];
    #pragma unroll
    for (int mt = 0; mt < 2; ++mt)
        #pragma unroll
        for (int nt = 0; nt < 8; ++nt)
            #pragma unroll
            for (int q = 0; q < 4; ++q) d[mt][nt][q] = 0.0f;

    #pragma unroll
    for (int ks = 0; ks < 4; ++ks) {
        uint4 av[2];
        #pragma unroll
        for (int mt = 0; mt < 2; ++mt)
            av[mt] = reinterpret_cast<const uint4*>(sAw)[
                (((2 * wid + mt) * 4 + ks) * 8 + g) * 4 + tig];
        #pragma unroll
        for (int nt = 0; nt < 8; ++nt) {
            ull bv = reinterpret_cast<const ull*>(sBw)[
                ((nt * 4 + ks) * 8 + g) * 4 + tig];
            uint32_t b0 = (uint32_t)bv, b1 = (uint32_t)(bv >> 32);
            #pragma unroll
            for (int mt = 0; mt < 2; ++mt)
                mma_f16(d[mt][nt], av[mt].x, av[mt].y, av[mt].z, av[mt].w, b0, b1);
        }
    }

    // ---- epilogue: bias + relu + W3 dot -> smem stage -> coalesced fnnT ----
    __syncthreads();                 // done reading sAw
    float* sFn = reinterpret_cast<float*>(sAw);
    const int rowBase = wid * 32;
    #pragma unroll
    for (int mt = 0; mt < 2; ++mt) {
        float s0 = 0.0f, s1 = 0.0f;
        #pragma unroll
        for (int nt = 0; nt < 8; ++nt) {
            int n0 = nt * 8 + 2 * tig;
            float bb0 = sb2[n0],     w30 = sw3[n0];
            float bb1 = sb2[n0 + 1], w31 = sw3[n0 + 1];
            s0 = fmaf(fmaxf(d[mt][nt][0] + bb0, 0.0f), w30, s0);
            s0 = fmaf(fmaxf(d[mt][nt][1] + bb1, 0.0f), w31, s0);
            s1 = fmaf(fmaxf(d[mt][nt][2] + bb0, 0.0f), w30, s1);
            s1 = fmaf(fmaxf(d[mt][nt][3] + bb1, 0.0f), w31, s1);
        }
        s0 += __shfl_xor_sync(0xFFFFFFFFu, s0, 1);
        s0 += __shfl_xor_sync(0xFFFFFFFFu, s0, 2);
        s1 += __shfl_xor_sync(0xFFFFFFFFu, s1, 1);
        s1 += __shfl_xor_sync(0xFFFFFFFFu, s1, 2);
        if (tig == 0) {
            int r = rowBase + mt * 16 + g;
            sFn[r]     = s0 + sb3v;
            sFn[r + 8] = s1 + sb3v;
        }
    }
    __syncthreads();
    g_fnnT[fB + yBase + tid] = sFn[tid];
}

// finish: per 32-batch tile, out[b] = sum_f fnnT[f][b]; transpose to fnn (B,F).
__global__ void nam_finish(float* __restrict__ out, float* __restrict__ fnn,
                           int B, int F)
{
    __shared__ float tile[FMAX][33];
    __shared__ float ps[8][32];

    const int b0 = blockIdx.x * 32;
    const int t  = threadIdx.x;          // 256
    const int bl = t & 31, fc = t >> 5;  // fc 0..7

    float s = 0.0f;
    #pragma unroll
    for (int i = 0; i < 16; ++i) {
        int f = fc * 16 + i;
        float v = g_fnnT[(size_t)f * B + b0 + bl];
        s += v;
        tile[f][bl] = v;
    }
    ps[fc][bl] = s;
    __syncthreads();

    if (t < 32) {
        float o = 0.0f;
        #pragma unroll
        for (int i = 0; i < 8; ++i) o += ps[i][t];
        out[b0 + t] = o;
    }

    const int col = t & 127, rr = t >> 7;
    #pragma unroll
    for (int r = 0; r < 32; r += 2)
        fnn[(size_t)(b0 + r + rr) * F + col] = tile[col][r + rr];
}

extern "C" void kernel_launch(void* const* d_in, const int* in_sizes, int n_in,
                              void* d_out, int out_size)
{
    const float* x  = (const float*)d_in[0];
    const float* W1 = (const float*)d_in[1];
    const float* b1 = (const float*)d_in[2];
    const float* W2 = (const float*)d_in[3];
    const float* b2 = (const float*)d_in[4];
    const float* W3 = (const float*)d_in[5];
    const float* b3 = (const float*)d_in[6];

    const int F = in_sizes[6];
    const int B = in_sizes[0] / F;

    float* out = (float*)d_out;   // (B,)
    float* fnn = out + B;         // (B, F)

    cudaFuncSetAttribute(nam_mma, cudaFuncAttributeMaxDynamicSharedMemorySize,
                         SMEM_BYTES);

    const int tBlocks = (F / 32) * (B / 32);
    nam_prep<<<F + tBlocks, 256>>>(W2, x, B, F);

    dim3 grid(F, B / MTILE);
    nam_mma<<<grid, THREADS, SMEM_BYTES>>>(W1, b1, b2, W3, b3, B, F);

    nam_finish<<<B / 32, 256>>>(out, fnn, B, F);
}